// round 16
// baseline (speedup 1.0000x reference)
#include <cuda_runtime.h>

#define TS   16     // samples per block
#define NT   512    // threads per block (16 warps)
#define NBLK 128    // 2048 / TS

__constant__ int c_FOFF[9] = {0,100000,150000,150010,150013,150113,150163,151163,151187};
__constant__ int c_EDIM[9] = {16,16,8,4,8,8,8,4,4};
__constant__ int c_EOFF[9] = {0,16,32,40,44,52,60,68,72};
#define NF_LAST 151192

struct P30 { const void* p[30]; };
typedef unsigned long long u64;

__device__ __forceinline__ void ffma2(u64 &d, u64 a, u64 b) {
    asm("fma.rn.f32x2 %0, %1, %2, %0;" : "+l"(d) : "l"(a), "l"(b));
}
__device__ __forceinline__ u64 pack2(float x) {
    u64 r; asm("mov.b64 %0, {%1, %1};" : "=l"(r) : "f"(x)); return r;
}
__device__ __forceinline__ float2 unpack2(u64 v) {
    float2 f; asm("mov.b64 {%0, %1}, %2;" : "=f"(f.x), "=f"(f.y) : "l"(v)); return f;
}
__device__ __forceinline__ int read_id(const void* p, int i, bool is64) {
    return is64 ? (int)((const long long*)p)[i] : ((const int*)p)[i];
}
__device__ __forceinline__ void bar256() {
    asm volatile("bar.sync 1, 256;" ::: "memory");
}

// static smem (all small now): activations only
extern "C" __global__ void __launch_bounds__(NT, 1)
deepfm_kernel(P30 a, float* __restrict__ out, int B)
{
    __shared__ __align__(16) float sXT [77 * 16];
    __shared__ __align__(16) float sH1T[256 * 16];
    __shared__ __align__(16) float sH2T[128 * 16];
    __shared__ __align__(16) float sH3T[64 * 16];
    __shared__ float sBase[TS];
    __shared__ float sPrice[TS];
    __shared__ int   sIdx[TS * 9];

    const int t  = threadIdx.x;
    const int w  = t >> 5;
    const int ln = t & 31;
    const int s0blk = blockIdx.x * TS;

    // ---- input-layout detection (deterministic, data-driven) ----
    const u64* u0 = (const u64*)a.p[0];
    const bool is64 = ((u0[0] | u0[1] | u0[2] | u0[3]) < (1ULL << 20));
    const u64* u7 = (const u64*)a.p[7];
    const bool dict = (u7[0] < (1ULL << 40));

    const void* idp[9];
    #pragma unroll
    for (int f = 0; f < 7; f++) idp[f] = a.p[f];
    const float* price;
    if (dict) { idp[7] = a.p[7]; idp[8] = a.p[8]; price = (const float*)a.p[9]; }
    else      { price = (const float*)a.p[7]; idp[7] = a.p[8]; idp[8] = a.p[9]; }

    const float* emb[9];
    #pragma unroll
    for (int f = 0; f < 9; f++) emb[f] = (const float*)a.p[10 + f];
    const float* __restrict__ w_dense = (const float*)a.p[19];
    const float* __restrict__ b_dense = (const float*)a.p[20];
    const float* __restrict__ fm_v    = (const float*)a.p[21];
    const float* __restrict__ W1 = (const float*)a.p[22];
    const float* __restrict__ b1 = (const float*)a.p[23];
    const float* __restrict__ W2 = (const float*)a.p[24];
    const float* __restrict__ b2 = (const float*)a.p[25];
    const float* __restrict__ W3 = (const float*)a.p[26];
    const float* __restrict__ b3 = (const float*)a.p[27];
    const float* __restrict__ Wo = (const float*)a.p[28];
    const float* __restrict__ bo = (const float*)a.p[29];

    // ---- gather ids + price ----
    if (t < TS * 9) {
        int s = t / 9, f = t - s * 9;
        sIdx[s * 9 + f] = read_id(idp[f], s0blk + s, is64);
    }
    if (t >= 160 && t < 160 + TS) sPrice[t - 160] = price[s0blk + (t - 160)];
    __syncthreads();

    // ---- warps 0-7: FM + dense; warps 8-15: build XT[77][16] ----
    if (w < 8) {
        int s = w * 2 + (ln >> 4);
        int e = ln & 15;
        float pv = sPrice[s] * 1e-3f;
        float fs = 0.f, ss = 0.f;
        #pragma unroll
        for (int f = 0; f < 9; f++) {
            int row = c_FOFF[f] + sIdx[s * 9 + f];
            float v = fm_v[row * 16 + e];
            fs += v; ss += v * v;
        }
        {
            float v = fm_v[NF_LAST * 16 + e];
            fs += pv * v; ss += pv * pv * v * v;
        }
        float val = fs * fs - ss;
        #pragma unroll
        for (int o = 8; o; o >>= 1) val += __shfl_xor_sync(0xffffffffu, val, o, 16);
        float fm = 0.5f * val;

        float dn = 0.f;
        if (e < 9)  dn = w_dense[c_FOFF[e] + sIdx[s * 9 + e]];
        if (e == 9) dn = pv * w_dense[NF_LAST];
        #pragma unroll
        for (int o = 8; o; o >>= 1) dn += __shfl_xor_sync(0xffffffffu, dn, o, 16);

        if (e == 0) sBase[s] = fm + dn + b_dense[0];
    } else {
        for (int idx = t - 256; idx < TS * 77; idx += 256) {
            int s = idx & 15, c = idx >> 4;
            float v;
            if (c == 76) v = sPrice[s];
            else {
                int f = 8;
                #pragma unroll
                for (int k = 8; k >= 1; k--) if (c < c_EOFF[k]) f = k - 1;
                v = emb[f][sIdx[s * 9 + f] * c_EDIM[f] + (c - c_EOFF[f])];
            }
            sXT[c * 16 + s] = v;
        }
    }
    __syncthreads();

    // ---- Layer 1: K=77, N=256, all 16 warps. 2 outs x 4 samples. W1 direct LDG. ----
    {
        int sg  = ln >> 3;                 // 0..3 -> s0 = sg*4
        int jgl = ln & 7;
        int j0  = (w * 8 + jgl) * 2;       // 0..254
        int s0  = sg * 4;
        float2 bv = *(const float2*)(b1 + j0);
        u64 acc[2][2];
        acc[0][0] = acc[0][1] = pack2(bv.x);
        acc[1][0] = acc[1][1] = pack2(bv.y);
        #pragma unroll 7
        for (int i = 0; i < 77; i++) {
            float2 wv = *(const float2*)(W1 + i * 256 + j0);
            double2 xv = *(const double2*)(sXT + i * 16 + s0);
            u64 x01 = __double_as_longlong(xv.x);
            u64 x23 = __double_as_longlong(xv.y);
            u64 w0 = pack2(wv.x), w1p = pack2(wv.y);
            ffma2(acc[0][0], w0,  x01); ffma2(acc[0][1], w0,  x23);
            ffma2(acc[1][0], w1p, x01); ffma2(acc[1][1], w1p, x23);
        }
        #pragma unroll
        for (int j = 0; j < 2; j++) {
            float2 lo = unpack2(acc[j][0]);
            float2 hi = unpack2(acc[j][1]);
            float4 o;
            o.x = fmaxf(lo.x, 0.f); o.y = fmaxf(lo.y, 0.f);
            o.z = fmaxf(hi.x, 0.f); o.w = fmaxf(hi.y, 0.f);
            *(float4*)(sH1T + (j0 + j) * 16 + s0) = o;
        }
    }
    __syncthreads();         // last full-block barrier; warps 8-15 retire

    if (w >= 8) return;

    // ================= tail: warps 0-7 (2 per SMSP), named barrier =================

    // ---- Layer 2: K=256, N=128, 8 warps. 2 outs x 4 samples. W2 DIRECT LDG. ----
    {
        int jgl = ln & 7;
        int sg  = ln >> 3;
        int j0  = w * 16 + jgl * 2;        // 0..126
        int s0  = sg * 4;
        float2 bv = *(const float2*)(b2 + j0);
        u64 acc[2][2];
        acc[0][0] = acc[0][1] = pack2(bv.x);
        acc[1][0] = acc[1][1] = pack2(bv.y);
        #pragma unroll 16
        for (int i = 0; i < 256; i++) {
            float2 wv = *(const float2*)(W2 + i * 128 + j0);   // gmem, L2-resident
            double2 xv = *(const double2*)(sH1T + i * 16 + s0);
            u64 x01 = __double_as_longlong(xv.x);
            u64 x23 = __double_as_longlong(xv.y);
            u64 w0 = pack2(wv.x), w1p = pack2(wv.y);
            ffma2(acc[0][0], w0,  x01); ffma2(acc[0][1], w0,  x23);
            ffma2(acc[1][0], w1p, x01); ffma2(acc[1][1], w1p, x23);
        }
        #pragma unroll
        for (int j = 0; j < 2; j++) {
            float2 lo = unpack2(acc[j][0]);
            float2 hi = unpack2(acc[j][1]);
            float4 o;
            o.x = fmaxf(lo.x, 0.f); o.y = fmaxf(lo.y, 0.f);
            o.z = fmaxf(hi.x, 0.f); o.w = fmaxf(hi.y, 0.f);
            *(float4*)(sH2T + (j0 + j) * 16 + s0) = o;
        }
    }
    bar256();

    // ---- Layer 3: K=128, N=64, 8 warps. 1 out x 4 samples. W3 DIRECT LDG. ----
    {
        int j  = w * 8 + (ln & 7);         // 0..63
        int s0 = (ln >> 3) * 4;
        u64 acc0, acc1;
        acc0 = acc1 = pack2(b3[j]);
        #pragma unroll 16
        for (int i = 0; i < 128; i++) {
            float wv = W3[i * 64 + j];                          // gmem, L2-resident
            double2 xv = *(const double2*)(sH2T + i * 16 + s0);
            u64 wp = pack2(wv);
            ffma2(acc0, wp, __double_as_longlong(xv.x));
            ffma2(acc1, wp, __double_as_longlong(xv.y));
        }
        float2 lo = unpack2(acc0);
        float2 hi = unpack2(acc1);
        float4 o;
        o.x = fmaxf(lo.x, 0.f); o.y = fmaxf(lo.y, 0.f);
        o.z = fmaxf(hi.x, 0.f); o.w = fmaxf(hi.y, 0.f);
        *(float4*)(sH3T + j * 16 + s0) = o;
    }
    bar256();

    // ---- Output: out[s] = H3[:,s] . Wo + bo + base ----
    if (t < TS) {
        int s = t;
        float v0 = 0.f, v1 = 0.f, v2 = 0.f, v3 = 0.f;
        #pragma unroll
        for (int j = 0; j < 64; j += 4) {
            v0 += sH3T[(j    ) * 16 + s] * Wo[j    ];
            v1 += sH3T[(j + 1) * 16 + s] * Wo[j + 1];
            v2 += sH3T[(j + 2) * 16 + s] * Wo[j + 2];
            v3 += sH3T[(j + 3) * 16 + s] * Wo[j + 3];
        }
        if (s0blk + s < B)
            out[s0blk + s] = (v0 + v1) + (v2 + v3) + bo[0] + sBase[s];
    }
}

extern "C" void kernel_launch(void* const* d_in, const int* in_sizes, int n_in,
                              void* d_out, int out_size)
{
    (void)in_sizes; (void)n_in;
    P30 a;
    for (int i = 0; i < 30; i++) a.p[i] = d_in[i];
    deepfm_kernel<<<NBLK, NT>>>(a, (float*)d_out, out_size);
}

// round 17
// speedup vs baseline: 1.0931x; 1.0931x over previous
#include <cuda_runtime.h>

#define TS   16     // samples per block
#define NT   512    // threads per block (16 warps)
#define NBLK 128    // 2048 / TS

__constant__ int c_FOFF[9] = {0,100000,150000,150010,150013,150113,150163,151163,151187};
__constant__ int c_EDIM[9] = {16,16,8,4,8,8,8,4,4};
__constant__ int c_EOFF[9] = {0,16,32,40,44,52,60,68,72};
#define NF_LAST 151192

struct P30 { const void* p[30]; };
typedef unsigned long long u64;

__device__ __forceinline__ void ffma2(u64 &d, u64 a, u64 b) {
    asm("fma.rn.f32x2 %0, %1, %2, %0;" : "+l"(d) : "l"(a), "l"(b));
}
__device__ __forceinline__ u64 pack2(float x) {
    u64 r; asm("mov.b64 %0, {%1, %1};" : "=l"(r) : "f"(x)); return r;
}
__device__ __forceinline__ float2 unpack2(u64 v) {
    float2 f; asm("mov.b64 {%0, %1}, %2;" : "=f"(f.x), "=f"(f.y) : "l"(v)); return f;
}
__device__ __forceinline__ int read_id(const void* p, int i, bool is64) {
    return is64 ? (int)((const long long*)p)[i] : ((const int*)p)[i];
}
__device__ __forceinline__ unsigned smem_u32(const void* p) {
    return (unsigned)__cvta_generic_to_shared(p);
}
__device__ __forceinline__ void cp16(void* dst, const void* src) {
    asm volatile("cp.async.cg.shared.global [%0], [%1], 16;\n"
                 :: "r"(smem_u32(dst)), "l"(src) : "memory");
}
__device__ __forceinline__ void cp_commit() {
    asm volatile("cp.async.commit_group;\n" ::: "memory");
}
template<int N> __device__ __forceinline__ void cp_wait() {
    asm volatile("cp.async.wait_group %0;\n" :: "n"(N) : "memory");
}
__device__ __forceinline__ void bar128() {
    asm volatile("bar.sync 1, 128;" ::: "memory");
}

// dynamic smem layout (floats):
//   [0, 32768)        sW2  (256x128)
//   [32768, 40960)    sW3  (128x64)
//   [40960, 42240)    sXT  (77x16, padded)
//   [42240, 46336)    sH1T (256x16)
//   [46336, 48384)    sH2T (128x16)
//   [48384, 49408)    sH3T (64x16)
//   [49408, 49424)    sBase
//   [49424, 49440)    sPrice
//   [49440, 49584)    sIdx (144 ints)
#define SMEM_FLOATS 49584
#define SMEM_BYTES  (SMEM_FLOATS * 4)

extern "C" __global__ void __launch_bounds__(NT, 1)
deepfm_kernel(P30 a, float* __restrict__ out, int B)
{
    extern __shared__ __align__(16) float sm[];
    float* sW2    = sm;
    float* sW3    = sm + 32768;
    float* sXT    = sm + 40960;
    float* sH1T   = sm + 42240;
    float* sH2T   = sm + 46336;
    float* sH3T   = sm + 48384;
    float* sBase  = sm + 49408;
    float* sPrice = sm + 49424;
    int*   sIdx   = (int*)(sm + 49440);

    const int t  = threadIdx.x;
    const int w  = t >> 5;
    const int ln = t & 31;
    const int s0blk = blockIdx.x * TS;

    // ---- input-layout detection (deterministic, data-driven) ----
    const u64* u0 = (const u64*)a.p[0];
    const bool is64 = ((u0[0] | u0[1] | u0[2] | u0[3]) < (1ULL << 20));
    const u64* u7 = (const u64*)a.p[7];
    const bool dict = (u7[0] < (1ULL << 40));

    const void* idp[9];
    #pragma unroll
    for (int f = 0; f < 7; f++) idp[f] = a.p[f];
    const float* price;
    if (dict) { idp[7] = a.p[7]; idp[8] = a.p[8]; price = (const float*)a.p[9]; }
    else      { price = (const float*)a.p[7]; idp[7] = a.p[8]; idp[8] = a.p[9]; }

    const float* emb[9];
    #pragma unroll
    for (int f = 0; f < 9; f++) emb[f] = (const float*)a.p[10 + f];
    const float* __restrict__ w_dense = (const float*)a.p[19];
    const float* __restrict__ b_dense = (const float*)a.p[20];
    const float* __restrict__ fm_v    = (const float*)a.p[21];
    const float* __restrict__ W1 = (const float*)a.p[22];
    const float* __restrict__ b1 = (const float*)a.p[23];
    const float* __restrict__ W2 = (const float*)a.p[24];
    const float* __restrict__ b2 = (const float*)a.p[25];
    const float* __restrict__ W3 = (const float*)a.p[26];
    const float* __restrict__ b3 = (const float*)a.p[27];
    const float* __restrict__ Wo = (const float*)a.p[28];
    const float* __restrict__ bo = (const float*)a.p[29];

    // ---- id/price gathers FIRST (they gate the first barrier; L1tex queue is FIFO) ----
    if (t < TS * 9) {
        int s = t / 9, f = t - s * 9;
        sIdx[s * 9 + f] = read_id(idp[f], s0blk + s, is64);
    }
    if (t >= 160 && t < 160 + TS) sPrice[t - 160] = price[s0blk + (t - 160)];

    // ---- async weight staging (overlaps gather + FM + L1; not needed until tail) ----
    {
        const float4* gW2 = (const float4*)W2;
        float4* dW2 = (float4*)sW2;
        #pragma unroll
        for (int k = 0; k < 16; k++) cp16(dW2 + t + k * NT, gW2 + t + k * NT);
        const float4* gW3 = (const float4*)W3;
        float4* dW3 = (float4*)sW3;
        #pragma unroll
        for (int k = 0; k < 4; k++) cp16(dW3 + t + k * NT, gW3 + t + k * NT);
        cp_commit();
    }
    __syncthreads();

    // ---- warps 0-7: FM + dense; warps 8-15: build XT[77][16] ----
    if (w < 8) {
        int s = w * 2 + (ln >> 4);
        int e = ln & 15;
        float pv = sPrice[s] * 1e-3f;
        float fs = 0.f, ss = 0.f;
        #pragma unroll
        for (int f = 0; f < 9; f++) {
            int row = c_FOFF[f] + sIdx[s * 9 + f];
            float v = fm_v[row * 16 + e];
            fs += v; ss += v * v;
        }
        {
            float v = fm_v[NF_LAST * 16 + e];
            fs += pv * v; ss += pv * pv * v * v;
        }
        float val = fs * fs - ss;
        #pragma unroll
        for (int o = 8; o; o >>= 1) val += __shfl_xor_sync(0xffffffffu, val, o, 16);
        float fm = 0.5f * val;

        float dn = 0.f;
        if (e < 9)  dn = w_dense[c_FOFF[e] + sIdx[s * 9 + e]];
        if (e == 9) dn = pv * w_dense[NF_LAST];
        #pragma unroll
        for (int o = 8; o; o >>= 1) dn += __shfl_xor_sync(0xffffffffu, dn, o, 16);

        if (e == 0) sBase[s] = fm + dn + b_dense[0];
    } else {
        for (int idx = t - 256; idx < TS * 77; idx += 256) {
            int s = idx & 15, c = idx >> 4;
            float v;
            if (c == 76) v = sPrice[s];
            else {
                int f = 8;
                #pragma unroll
                for (int k = 8; k >= 1; k--) if (c < c_EOFF[k]) f = k - 1;
                v = emb[f][sIdx[s * 9 + f] * c_EDIM[f] + (c - c_EOFF[f])];
            }
            sXT[c * 16 + s] = v;
        }
    }
    __syncthreads();

    // ---- Layer 1: K=77, N=256, all 16 warps. 2 outs x 4 samples. W1 direct LDG. ----
    {
        int sg  = ln >> 3;                 // 0..3 -> s0 = sg*4
        int jgl = ln & 7;
        int j0  = (w * 8 + jgl) * 2;       // 0..254
        int s0  = sg * 4;
        float2 bv = *(const float2*)(b1 + j0);
        u64 acc[2][2];
        acc[0][0] = acc[0][1] = pack2(bv.x);
        acc[1][0] = acc[1][1] = pack2(bv.y);
        #pragma unroll 11
        for (int i = 0; i < 77; i++) {
            float2 wv = *(const float2*)(W1 + i * 256 + j0);
            double2 xv = *(const double2*)(sXT + i * 16 + s0);
            u64 x01 = __double_as_longlong(xv.x);
            u64 x23 = __double_as_longlong(xv.y);
            u64 w0 = pack2(wv.x), w1p = pack2(wv.y);
            ffma2(acc[0][0], w0,  x01); ffma2(acc[0][1], w0,  x23);
            ffma2(acc[1][0], w1p, x01); ffma2(acc[1][1], w1p, x23);
        }
        #pragma unroll
        for (int j = 0; j < 2; j++) {
            float2 lo = unpack2(acc[j][0]);
            float2 hi = unpack2(acc[j][1]);
            float4 o;
            o.x = fmaxf(lo.x, 0.f); o.y = fmaxf(lo.y, 0.f);
            o.z = fmaxf(hi.x, 0.f); o.w = fmaxf(hi.y, 0.f);
            *(float4*)(sH1T + (j0 + j) * 16 + s0) = o;
        }
    }
    cp_wait<0>();            // W2 + W3 resident
    __syncthreads();         // last full-block barrier; warps 4-15 retire after this

    if (w < 4) {
        const int jq = ln >> 2;            // 0..7
        const int sg = ln & 3;
        const int s0 = sg * 4;

        // ---- Layer 2: K=256, N=128, warps 0-3. 4 outs x 4 samples, smem W2. ----
        {
            int j0 = (w * 8 + jq) * 4;     // 0..124
            float4 bv = *(const float4*)(b2 + j0);
            u64 acc[4][2];
            acc[0][0] = acc[0][1] = pack2(bv.x);
            acc[1][0] = acc[1][1] = pack2(bv.y);
            acc[2][0] = acc[2][1] = pack2(bv.z);
            acc[3][0] = acc[3][1] = pack2(bv.w);
            #pragma unroll 8
            for (int i = 0; i < 256; i++) {
                float4 wv = *(const float4*)(sW2 + i * 128 + j0);
                double2 xv = *(const double2*)(sH1T + i * 16 + s0);
                u64 x01 = __double_as_longlong(xv.x);
                u64 x23 = __double_as_longlong(xv.y);
                u64 w0 = pack2(wv.x), w1p = pack2(wv.y);
                u64 w2p = pack2(wv.z), w3p = pack2(wv.w);
                ffma2(acc[0][0], w0,  x01); ffma2(acc[0][1], w0,  x23);
                ffma2(acc[1][0], w1p, x01); ffma2(acc[1][1], w1p, x23);
                ffma2(acc[2][0], w2p, x01); ffma2(acc[2][1], w2p, x23);
                ffma2(acc[3][0], w3p, x01); ffma2(acc[3][1], w3p, x23);
            }
            #pragma unroll
            for (int j = 0; j < 4; j++) {
                float2 lo = unpack2(acc[j][0]);
                float2 hi = unpack2(acc[j][1]);
                float4 o;
                o.x = fmaxf(lo.x, 0.f); o.y = fmaxf(lo.y, 0.f);
                o.z = fmaxf(hi.x, 0.f); o.w = fmaxf(hi.y, 0.f);
                *(float4*)(sH2T + (j0 + j) * 16 + s0) = o;
            }
        }
        bar128();

        // ---- Layer 3: K=128, N=64, warps 0-3. 2 outs x 4 samples, smem W3. ----
        {
            int j0 = (w * 8 + jq) * 2;     // 0..62
            float2 bv = *(const float2*)(b3 + j0);
            u64 acc[2][2];
            acc[0][0] = acc[0][1] = pack2(bv.x);
            acc[1][0] = acc[1][1] = pack2(bv.y);
            #pragma unroll 8
            for (int i = 0; i < 128; i++) {
                float2 wv = *(const float2*)(sW3 + i * 64 + j0);
                double2 xv = *(const double2*)(sH2T + i * 16 + s0);
                u64 x01 = __double_as_longlong(xv.x);
                u64 x23 = __double_as_longlong(xv.y);
                u64 w0 = pack2(wv.x), w1p = pack2(wv.y);
                ffma2(acc[0][0], w0,  x01); ffma2(acc[0][1], w0,  x23);
                ffma2(acc[1][0], w1p, x01); ffma2(acc[1][1], w1p, x23);
            }
            #pragma unroll
            for (int j = 0; j < 2; j++) {
                float2 lo = unpack2(acc[j][0]);
                float2 hi = unpack2(acc[j][1]);
                float4 o;
                o.x = fmaxf(lo.x, 0.f); o.y = fmaxf(lo.y, 0.f);
                o.z = fmaxf(hi.x, 0.f); o.w = fmaxf(hi.y, 0.f);
                *(float4*)(sH3T + (j0 + j) * 16 + s0) = o;
            }
        }
        bar128();

        // ---- Output: out[s] = H3[:,s] . Wo + bo + base ----
        if (t < TS) {
            int s = t;
            float v0 = 0.f, v1 = 0.f, v2 = 0.f, v3 = 0.f;
            #pragma unroll
            for (int j = 0; j < 64; j += 4) {
                v0 += sH3T[(j    ) * 16 + s] * Wo[j    ];
                v1 += sH3T[(j + 1) * 16 + s] * Wo[j + 1];
                v2 += sH3T[(j + 2) * 16 + s] * Wo[j + 2];
                v3 += sH3T[(j + 3) * 16 + s] * Wo[j + 3];
            }
            if (s0blk + s < B)
                out[s0blk + s] = (v0 + v1) + (v2 + v3) + bo[0] + sBase[s];
        }
    }
}

extern "C" void kernel_launch(void* const* d_in, const int* in_sizes, int n_in,
                              void* d_out, int out_size)
{
    (void)in_sizes; (void)n_in;
    P30 a;
    for (int i = 0; i < 30; i++) a.p[i] = d_in[i];
    cudaFuncSetAttribute(deepfm_kernel, cudaFuncAttributeMaxDynamicSharedMemorySize, SMEM_BYTES);
    deepfm_kernel<<<NBLK, NT, SMEM_BYTES>>>(a, (float*)d_out, out_size);
}